// round 1
// baseline (speedup 1.0000x reference)
#include <cuda_runtime.h>
#include <cuda_bf16.h>
#include <cstddef>

#define D_MODEL 512
#define NHEAD   8
#define HD      64
#define WIN     32
#define B_      2
#define S_      2048
#define MTOT    (B_ * S_)   // 4096

// Scratch (device globals: allocation-free per harness rules)
__device__ float g_qkv[(size_t)MTOT * 3 * D_MODEL];  // [B,S,3,H,hd] flattened = [4096,1536]
__device__ float g_att[(size_t)MTOT * D_MODEL];      // [4096,512]

// ---------------------------------------------------------------------------
// SGEMM: C[M,N] = A[M,K] @ B[K,N] + bias[N]
// BM=BN=128, BK=8, TM=TN=8, 256 threads. M,N,K all divisible by tile dims.
// ---------------------------------------------------------------------------
__global__ __launch_bounds__(256)
void sgemm_bias(int M, int N, int K,
                const float* __restrict__ A,
                const float* __restrict__ Bm,
                const float* __restrict__ bias,
                float* __restrict__ C)
{
    constexpr int BM = 128, BN = 128, BK = 8, TM = 8, TN = 8;
    __shared__ float As[BK][BM];
    __shared__ float Bs[BK][BN];

    const int tid = threadIdx.x;
    const int bx = blockIdx.x, by = blockIdx.y;

    const int threadCol = tid % (BN / TN);   // 0..15
    const int threadRow = tid / (BN / TN);   // 0..15

    const float* Ab = A + (size_t)by * BM * K;
    const float* Bb = Bm + (size_t)bx * BN;

    // A tile: 128x8 -> 256 float4 loads, one per thread
    const int innerRowA = tid / (BK / 4);          // 0..127
    const int innerColA = (tid % (BK / 4)) * 4;    // 0 or 4
    // B tile: 8x128 -> 256 float4 loads, one per thread
    const int innerRowB = tid / (BN / 4);          // 0..7
    const int innerColB = (tid % (BN / 4)) * 4;    // 0..124

    float acc[TM][TN] = {};
    float regM[TM], regN[TN];

    for (int k0 = 0; k0 < K; k0 += BK) {
        float4 a = *(const float4*)(Ab + (size_t)innerRowA * K + k0 + innerColA);
        As[innerColA + 0][innerRowA] = a.x;
        As[innerColA + 1][innerRowA] = a.y;
        As[innerColA + 2][innerRowA] = a.z;
        As[innerColA + 3][innerRowA] = a.w;

        float4 b = *(const float4*)(Bb + (size_t)(k0 + innerRowB) * N + innerColB);
        *(float4*)&Bs[innerRowB][innerColB] = b;

        __syncthreads();

        #pragma unroll
        for (int kk = 0; kk < BK; kk++) {
            *(float4*)&regM[0] = *(float4*)&As[kk][threadRow * TM];
            *(float4*)&regM[4] = *(float4*)&As[kk][threadRow * TM + 4];
            *(float4*)&regN[0] = *(float4*)&Bs[kk][threadCol * TN];
            *(float4*)&regN[4] = *(float4*)&Bs[kk][threadCol * TN + 4];
            #pragma unroll
            for (int i = 0; i < TM; i++)
                #pragma unroll
                for (int j = 0; j < TN; j++)
                    acc[i][j] += regM[i] * regN[j];
        }
        __syncthreads();
    }

    float* Cb = C + (size_t)by * BM * N + (size_t)bx * BN;
    #pragma unroll
    for (int i = 0; i < TM; i++) {
        int row = threadRow * TM + i;
        #pragma unroll
        for (int j = 0; j < TN; j += 4) {
            int col = threadCol * TN + j;
            float4 o;
            o.x = acc[i][j + 0] + bias[bx * BN + col + 0];
            o.y = acc[i][j + 1] + bias[bx * BN + col + 1];
            o.z = acc[i][j + 2] + bias[bx * BN + col + 2];
            o.w = acc[i][j + 3] + bias[bx * BN + col + 3];
            *(float4*)(Cb + (size_t)row * N + col) = o;
        }
    }
}

// ---------------------------------------------------------------------------
// Sliding-window attention.
// Grid: (S/16, H, B). 256 threads = 8 warps, each warp handles 2 queries.
// K/V window [t0-32, t0+47] (80 rows) staged to SMEM.
// Lane-per-score layout: ks padded to 65 floats/row for conflict-free
// column access across rows. vs unpadded (row-fixed access).
// ---------------------------------------------------------------------------
__global__ __launch_bounds__(256)
void swin_attn(const float* __restrict__ qkv, float* __restrict__ att)
{
    const int t0 = blockIdx.x * 16;
    const int h  = blockIdx.y;
    const int b  = blockIdx.z;

    __shared__ float ks[80][HD + 1];
    __shared__ float vs[80][HD];
    __shared__ float qs[8][HD];

    const int tid = threadIdx.x;

    // Stage K/V window rows [t0-32, t0+47]; out-of-range rows zero-filled.
    for (int i = tid; i < 80 * 16; i += 256) {
        int r  = i >> 4;
        int c4 = (i & 15) << 2;
        int sg = t0 - 32 + r;
        float4 k4 = make_float4(0.f, 0.f, 0.f, 0.f);
        float4 v4 = k4;
        if (sg >= 0 && sg < S_) {
            const float* base = qkv + ((size_t)(b * S_ + sg) * 3) * D_MODEL + h * HD;
            k4 = *(const float4*)(base + D_MODEL + c4);       // K part
            v4 = *(const float4*)(base + 2 * D_MODEL + c4);   // V part
        }
        ks[r][c4 + 0] = k4.x; ks[r][c4 + 1] = k4.y;
        ks[r][c4 + 2] = k4.z; ks[r][c4 + 3] = k4.w;
        *(float4*)&vs[r][c4] = v4;
    }
    __syncthreads();

    const int warp = tid >> 5, lane = tid & 31;
    const float scale = 0.125f;   // 1/sqrt(64)

    for (int qi = 0; qi < 2; qi++) {
        const int sl = warp * 2 + qi;   // local query 0..15
        const int s  = t0 + sl;

        // Stage q for this query into per-warp smem (broadcast reads later)
        const float* qptr = qkv + ((size_t)(b * S_ + s) * 3) * D_MODEL + h * HD;
        qs[warp][2 * lane]     = qptr[2 * lane];
        qs[warp][2 * lane + 1] = qptr[2 * lane + 1];
        __syncwarp();

        // Scores: lane computes window offsets j = lane, 32+lane, 64 (lane 0)
        float sc0 = 0.f, sc1 = 0.f, sc2 = 0.f;
        const int r0 = sl + lane;
        const int r1 = sl + 32 + lane;
        const int r2 = min(sl + 64 + lane, 79);
        #pragma unroll 16
        for (int d = 0; d < HD; d++) {
            float qv = qs[warp][d];
            sc0 += qv * ks[r0][d];
            sc1 += qv * ks[r1][d];
            sc2 += qv * ks[r2][d];
        }
        const int sg0 = s - 32 + lane;
        const int sg1 = sg0 + 32;
        const int sg2 = sg0 + 64;
        sc0 = (sg0 >= 0 && sg0 < S_) ? sc0 * scale : -1e30f;
        sc1 = (sg1 >= 0 && sg1 < S_) ? sc1 * scale : -1e30f;
        sc2 = (lane == 0 && sg2 >= 0 && sg2 < S_) ? sc2 * scale : -1e30f;

        // Softmax across the warp
        float m = fmaxf(sc0, fmaxf(sc1, sc2));
        #pragma unroll
        for (int o = 16; o > 0; o >>= 1)
            m = fmaxf(m, __shfl_xor_sync(0xffffffffu, m, o));
        float e0 = __expf(sc0 - m);
        float e1 = __expf(sc1 - m);
        float e2 = __expf(sc2 - m);
        float ssum = e0 + e1 + e2;
        #pragma unroll
        for (int o = 16; o > 0; o >>= 1)
            ssum += __shfl_xor_sync(0xffffffffu, ssum, o);
        const float inv = 1.0f / ssum;

        // AV: lane owns output dims 2*lane, 2*lane+1
        float o0 = 0.f, o1 = 0.f;
        #pragma unroll
        for (int j = 0; j < 65; j++) {
            float e = (j < 32) ? e0 : ((j < 64) ? e1 : e2);
            float p = __shfl_sync(0xffffffffu, e, j & 31);
            int r = sl + j;
            o0 += p * vs[r][2 * lane];
            o1 += p * vs[r][2 * lane + 1];
        }
        o0 *= inv; o1 *= inv;

        float* optr = att + (size_t)(b * S_ + s) * D_MODEL + h * HD;
        optr[2 * lane]     = o0;
        optr[2 * lane + 1] = o1;
        __syncwarp();
    }
}

// ---------------------------------------------------------------------------
extern "C" void kernel_launch(void* const* d_in, const int* in_sizes, int n_in,
                              void* d_out, int out_size)
{
    const float* x     = (const float*)d_in[0];  // [2,2048,512]
    const float* w_qkv = (const float*)d_in[1];  // [512,1536]
    const float* b_qkv = (const float*)d_in[2];  // [1536]
    const float* w_out = (const float*)d_in[3];  // [512,512]
    const float* b_out = (const float*)d_in[4];  // [512]
    float* out = (float*)d_out;                  // [2,2048,512]

    float* qkv = nullptr;
    float* att = nullptr;
    cudaGetSymbolAddress((void**)&qkv, g_qkv);
    cudaGetSymbolAddress((void**)&att, g_att);

    // 1) QKV projection: [4096,512] @ [512,1536] + bias
    {
        dim3 grid(3 * D_MODEL / 128, MTOT / 128);
        sgemm_bias<<<grid, 256>>>(MTOT, 3 * D_MODEL, D_MODEL, x, w_qkv, b_qkv, qkv);
    }

    // 2) Sliding-window attention
    {
        dim3 grid(S_ / 16, NHEAD, B_);
        swin_attn<<<grid, 256>>>(qkv, att);
    }

    // 3) Output projection: [4096,512] @ [512,512] + bias
    {
        dim3 grid(D_MODEL / 128, MTOT / 128);
        sgemm_bias<<<grid, 256>>>(MTOT, D_MODEL, D_MODEL, att, w_out, b_out, out);
    }
}

// round 5
// speedup vs baseline: 1.8410x; 1.8410x over previous
#include <cuda_runtime.h>
#include <cuda_bf16.h>
#include <cstdint>
#include <cstddef>

#define D_MODEL 512
#define NHEAD   8
#define HD      64
#define WIN     32
#define B_      2
#define S_      2048
#define MTOT    (B_ * S_)   // 4096
#define KDIM    512

// Scratch (device globals: allocation-free per harness rules)
__device__ float g_qkv[(size_t)MTOT * 3 * D_MODEL];      // [4096,1536]
__device__ float g_att[(size_t)MTOT * D_MODEL];          // [4096,512]
__device__ float g_wqkvT[(size_t)3 * D_MODEL * D_MODEL]; // [1536,512]
__device__ float g_woutT[(size_t)D_MODEL * D_MODEL];     // [512,512]

__device__ __forceinline__ uint32_t f2tf32(float f) {
    uint32_t u;
    asm("cvt.rna.tf32.f32 %0, %1;" : "=r"(u) : "f"(f));
    return u;
}

__device__ __forceinline__ void mma_tf32(float d[4], const uint32_t a[4], const uint32_t b[2]) {
    asm volatile(
        "mma.sync.aligned.m16n8k8.row.col.f32.tf32.tf32.f32 "
        "{%0,%1,%2,%3}, {%4,%5,%6,%7}, {%8,%9}, {%0,%1,%2,%3};"
        : "+f"(d[0]), "+f"(d[1]), "+f"(d[2]), "+f"(d[3])
        : "r"(a[0]), "r"(a[1]), "r"(a[2]), "r"(a[3]), "r"(b[0]), "r"(b[1]));
}

// ---------------------------------------------------------------------------
// Transpose: out[C][R] = in[R][C]^T   (R,C multiples of 32)
// ---------------------------------------------------------------------------
__global__ __launch_bounds__(256)
void transpose_k(const float* __restrict__ in, float* __restrict__ out, int R, int C)
{
    __shared__ float t[32][33];
    const int bx = blockIdx.x * 32;  // col block (in)
    const int by = blockIdx.y * 32;  // row block (in)
    const int x = bx + threadIdx.x;
    for (int i = threadIdx.y; i < 32; i += 8)
        t[i][threadIdx.x] = in[(size_t)(by + i) * C + x];
    __syncthreads();
    const int xo = by + threadIdx.x;
    for (int i = threadIdx.y; i < 32; i += 8)
        out[(size_t)(bx + i) * R + xo] = t[threadIdx.x][i];
}

// ---------------------------------------------------------------------------
// tf32 mma.sync GEMM: C[M,N] = A[M,512] @ BT[N,512]^T + bias[N]
// BM=BN=128, BK=16, 8 warps (2x4), warp tile 64x32, m16n8k8 fragments.
// Single smem stage + register prefetch. grid = (N/128, M/128).
// ---------------------------------------------------------------------------
template <int N>
__global__ __launch_bounds__(256)
void gemm_tf32mma(const float* __restrict__ A, const float* __restrict__ BT,
                  const float* __restrict__ bias, float* __restrict__ C)
{
    constexpr int BKP = 20;   // 16 + 4 pad: conflict-free fragment loads
    __shared__ float As[128][BKP];
    __shared__ float Bs[128][BKP];

    const int tid  = threadIdx.x;
    const int wid  = tid >> 5;
    const int lane = tid & 31;
    const int wm   = wid >> 2;        // 0..1
    const int wn   = wid & 3;         // 0..3
    const int g    = lane >> 2;       // group 0..7
    const int t    = lane & 3;        // thread-in-group

    const int m0 = blockIdx.y * 128;
    const int n0 = blockIdx.x * 128;

    // Global load mapping: thread -> rows (tid>>2) and (tid>>2)+64, cols (tid&3)*4..+3
    const int lrow = tid >> 2;            // 0..63
    const int lcol = (tid & 3) * 4;       // 0,4,8,12
    const float* Aptr = A  + (size_t)(m0 + lrow) * KDIM + lcol;
    const float* Bptr = BT + (size_t)(n0 + lrow) * KDIM + lcol;

    float4 pa0 = *(const float4*)(Aptr);
    float4 pa1 = *(const float4*)(Aptr + (size_t)64 * KDIM);
    float4 pb0 = *(const float4*)(Bptr);
    float4 pb1 = *(const float4*)(Bptr + (size_t)64 * KDIM);

    float acc[4][4][4] = {};

    constexpr int NCHUNK = KDIM / 16;   // 32
    #pragma unroll 1
    for (int kc = 0; kc < NCHUNK; kc++) {
        // Store prefetched chunk to smem with tf32 rounding
        uint32_t* a0 = (uint32_t*)&As[lrow][lcol];
        a0[0] = f2tf32(pa0.x); a0[1] = f2tf32(pa0.y); a0[2] = f2tf32(pa0.z); a0[3] = f2tf32(pa0.w);
        uint32_t* a1 = (uint32_t*)&As[lrow + 64][lcol];
        a1[0] = f2tf32(pa1.x); a1[1] = f2tf32(pa1.y); a1[2] = f2tf32(pa1.z); a1[3] = f2tf32(pa1.w);
        uint32_t* b0 = (uint32_t*)&Bs[lrow][lcol];
        b0[0] = f2tf32(pb0.x); b0[1] = f2tf32(pb0.y); b0[2] = f2tf32(pb0.z); b0[3] = f2tf32(pb0.w);
        uint32_t* b1 = (uint32_t*)&Bs[lrow + 64][lcol];
        b1[0] = f2tf32(pb1.x); b1[1] = f2tf32(pb1.y); b1[2] = f2tf32(pb1.z); b1[3] = f2tf32(pb1.w);
        __syncthreads();

        if (kc + 1 < NCHUNK) {
            Aptr += 16; Bptr += 16;
            pa0 = *(const float4*)(Aptr);
            pa1 = *(const float4*)(Aptr + (size_t)64 * KDIM);
            pb0 = *(const float4*)(Bptr);
            pb1 = *(const float4*)(Bptr + (size_t)64 * KDIM);
        }

        // Compute: 2 k-steps of 8
        #pragma unroll
        for (int ks = 0; ks < 2; ks++) {
            const int kb = ks * 8;
            uint32_t af[4][4], bf[4][2];
            #pragma unroll
            for (int mi = 0; mi < 4; mi++) {
                const int r = wm * 64 + mi * 16 + g;
                af[mi][0] = __float_as_uint(As[r][kb + t]);
                af[mi][1] = __float_as_uint(As[r + 8][kb + t]);
                af[mi][2] = __float_as_uint(As[r][kb + t + 4]);
                af[mi][3] = __float_as_uint(As[r + 8][kb + t + 4]);
            }
            #pragma unroll
            for (int ni = 0; ni < 4; ni++) {
                const int nr = wn * 32 + ni * 8 + g;
                bf[ni][0] = __float_as_uint(Bs[nr][kb + t]);
                bf[ni][1] = __float_as_uint(Bs[nr][kb + t + 4]);
            }
            #pragma unroll
            for (int mi = 0; mi < 4; mi++)
                #pragma unroll
                for (int ni = 0; ni < 4; ni++)
                    mma_tf32(acc[mi][ni], af[mi], bf[ni]);
        }
        __syncthreads();
    }

    // Epilogue: d0 at (g, 2t), d1 (g, 2t+1), d2 (g+8, 2t), d3 (g+8, 2t+1)
    #pragma unroll
    for (int mi = 0; mi < 4; mi++) {
        const int r = m0 + wm * 64 + mi * 16 + g;
        #pragma unroll
        for (int ni = 0; ni < 4; ni++) {
            const int c = n0 + wn * 32 + ni * 8 + 2 * t;
            const float bx0 = bias[c], bx1 = bias[c + 1];
            float2 v0 = make_float2(acc[mi][ni][0] + bx0, acc[mi][ni][1] + bx1);
            float2 v1 = make_float2(acc[mi][ni][2] + bx0, acc[mi][ni][3] + bx1);
            *(float2*)(C + (size_t)r * N + c)       = v0;
            *(float2*)(C + (size_t)(r + 8) * N + c) = v1;
        }
    }
}

// ---------------------------------------------------------------------------
// Sliding-window attention (fp32).
// ---------------------------------------------------------------------------
__global__ __launch_bounds__(256)
void swin_attn(const float* __restrict__ qkv, float* __restrict__ att)
{
    const int t0 = blockIdx.x * 16;
    const int h  = blockIdx.y;
    const int b  = blockIdx.z;

    __shared__ float ks[80][HD + 1];
    __shared__ float vs[80][HD];
    __shared__ float qs[8][HD];

    const int tid = threadIdx.x;

    for (int i = tid; i < 80 * 16; i += 256) {
        int r  = i >> 4;
        int c4 = (i & 15) << 2;
        int sg = t0 - 32 + r;
        float4 k4 = make_float4(0.f, 0.f, 0.f, 0.f);
        float4 v4 = k4;
        if (sg >= 0 && sg < S_) {
            const float* base = qkv + ((size_t)(b * S_ + sg) * 3) * D_MODEL + h * HD;
            k4 = *(const float4*)(base + D_MODEL + c4);
            v4 = *(const float4*)(base + 2 * D_MODEL + c4);
        }
        ks[r][c4 + 0] = k4.x; ks[r][c4 + 1] = k4.y;
        ks[r][c4 + 2] = k4.z; ks[r][c4 + 3] = k4.w;
        *(float4*)&vs[r][c4] = v4;
    }
    __syncthreads();

    const int warp = tid >> 5, lane = tid & 31;
    const float scale = 0.125f;

    for (int qi = 0; qi < 2; qi++) {
        const int sl = warp * 2 + qi;
        const int s  = t0 + sl;

        const float* qptr = qkv + ((size_t)(b * S_ + s) * 3) * D_MODEL + h * HD;
        qs[warp][2 * lane]     = qptr[2 * lane];
        qs[warp][2 * lane + 1] = qptr[2 * lane + 1];
        __syncwarp();

        float sc0 = 0.f, sc1 = 0.f, sc2 = 0.f;
        const int r0 = sl + lane;
        const int r1 = sl + 32 + lane;
        const int r2 = min(sl + 64 + lane, 79);
        #pragma unroll 16
        for (int d = 0; d < HD; d++) {
            float qv = qs[warp][d];
            sc0 += qv * ks[r0][d];
            sc1 += qv * ks[r1][d];
            sc2 += qv * ks[r2][d];
        }
        const int sg0 = s - 32 + lane;
        const int sg1 = sg0 + 32;
        const int sg2 = sg0 + 64;
        sc0 = (sg0 >= 0 && sg0 < S_) ? sc0 * scale : -1e30f;
        sc1 = (sg1 >= 0 && sg1 < S_) ? sc1 * scale : -1e30f;
        sc2 = (lane == 0 && sg2 >= 0 && sg2 < S_) ? sc2 * scale : -1e30f;

        float m = fmaxf(sc0, fmaxf(sc1, sc2));
        #pragma unroll
        for (int o = 16; o > 0; o >>= 1)
            m = fmaxf(m, __shfl_xor_sync(0xffffffffu, m, o));
        float e0 = __expf(sc0 - m);
        float e1 = __expf(sc1 - m);
        float e2 = __expf(sc2 - m);
        float ssum = e0 + e1 + e2;
        #pragma unroll
        for (int o = 16; o > 0; o >>= 1)
            ssum += __shfl_xor_sync(0xffffffffu, ssum, o);
        const float inv = 1.0f / ssum;

        float o0 = 0.f, o1 = 0.f;
        #pragma unroll
        for (int j = 0; j < 65; j++) {
            float e = (j < 32) ? e0 : ((j < 64) ? e1 : e2);
            float p = __shfl_sync(0xffffffffu, e, j & 31);
            int r = sl + j;
            o0 += p * vs[r][2 * lane];
            o1 += p * vs[r][2 * lane + 1];
        }
        o0 *= inv; o1 *= inv;

        float* optr = att + (size_t)(b * S_ + s) * D_MODEL + h * HD;
        optr[2 * lane]     = o0;
        optr[2 * lane + 1] = o1;
        __syncwarp();
    }
}

// ---------------------------------------------------------------------------
extern "C" void kernel_launch(void* const* d_in, const int* in_sizes, int n_in,
                              void* d_out, int out_size)
{
    const float* x     = (const float*)d_in[0];
    const float* w_qkv = (const float*)d_in[1];
    const float* b_qkv = (const float*)d_in[2];
    const float* w_out = (const float*)d_in[3];
    const float* b_out = (const float*)d_in[4];
    float* out = (float*)d_out;

    float *qkv, *att, *wqkvT, *woutT;
    cudaGetSymbolAddress((void**)&qkv, g_qkv);
    cudaGetSymbolAddress((void**)&att, g_att);
    cudaGetSymbolAddress((void**)&wqkvT, g_wqkvT);
    cudaGetSymbolAddress((void**)&woutT, g_woutT);

    // 0) Transpose weights: [K,N] -> [N,K]
    transpose_k<<<dim3(48, 16), dim3(32, 8)>>>(w_qkv, wqkvT, D_MODEL, 3 * D_MODEL);
    transpose_k<<<dim3(16, 16), dim3(32, 8)>>>(w_out, woutT, D_MODEL, D_MODEL);

    // 1) QKV projection: [4096,512] @ [512,1536] + bias
    gemm_tf32mma<1536><<<dim3(12, 32), 256>>>(x, wqkvT, b_qkv, qkv);

    // 2) Sliding-window attention
    swin_attn<<<dim3(S_ / 16, NHEAD, B_), 256>>>(qkv, att);

    // 3) Output projection: [4096,512] @ [512,512] + bias
    gemm_tf32mma<512><<<dim3(4, 32), 256>>>(att, woutT, b_out, out);
}

// round 6
// speedup vs baseline: 2.0960x; 1.1385x over previous
#include <cuda_runtime.h>
#include <cuda_bf16.h>
#include <cstdint>
#include <cstddef>

#define D_MODEL 512
#define NHEAD   8
#define HD      64
#define WIN     32
#define B_      2
#define S_      2048
#define MTOT    (B_ * S_)   // 4096
#define KDIM    512

// Scratch (device globals: allocation-free per harness rules)
__device__ float g_qkv[(size_t)MTOT * 3 * D_MODEL];      // [4096,1536]
__device__ float g_att[(size_t)MTOT * D_MODEL];          // [4096,512]
__device__ float g_wqkvT[(size_t)3 * D_MODEL * D_MODEL]; // [1536,512]
__device__ float g_woutT[(size_t)D_MODEL * D_MODEL];     // [512,512]

__device__ __forceinline__ uint32_t f2tf32(float f) {
    uint32_t u;
    asm("cvt.rna.tf32.f32 %0, %1;" : "=r"(u) : "f"(f));
    return u;
}

__device__ __forceinline__ void mma_tf32(float d[4], const uint32_t a[4], const uint32_t b[2]) {
    asm volatile(
        "mma.sync.aligned.m16n8k8.row.col.f32.tf32.tf32.f32 "
        "{%0,%1,%2,%3}, {%4,%5,%6,%7}, {%8,%9}, {%0,%1,%2,%3};"
        : "+f"(d[0]), "+f"(d[1]), "+f"(d[2]), "+f"(d[3])
        : "r"(a[0]), "r"(a[1]), "r"(a[2]), "r"(a[3]), "r"(b[0]), "r"(b[1]));
}

// ---------------------------------------------------------------------------
// Transpose: out[C][R] = in[R][C]^T   (R,C multiples of 32)
// ---------------------------------------------------------------------------
__global__ __launch_bounds__(256)
void transpose_k(const float* __restrict__ in, float* __restrict__ out, int R, int C)
{
    __shared__ float t[32][33];
    const int bx = blockIdx.x * 32;  // col block (in)
    const int by = blockIdx.y * 32;  // row block (in)
    const int x = bx + threadIdx.x;
    for (int i = threadIdx.y; i < 32; i += 8)
        t[i][threadIdx.x] = in[(size_t)(by + i) * C + x];
    __syncthreads();
    const int xo = by + threadIdx.x;
    for (int i = threadIdx.y; i < 32; i += 8)
        out[(size_t)(bx + i) * R + xo] = t[threadIdx.x][i];
}

// ---------------------------------------------------------------------------
// tf32 mma.sync GEMM: C[M,N] = A[M,512] @ BT[N,512]^T + bias[N]
// BM=BN=128, BK=16, 8 warps (2x4), warp tile 64x32, m16n8k8 fragments.
// ---------------------------------------------------------------------------
template <int N>
__global__ __launch_bounds__(256)
void gemm_tf32mma(const float* __restrict__ A, const float* __restrict__ BT,
                  const float* __restrict__ bias, float* __restrict__ C)
{
    constexpr int BKP = 20;   // 16 + 4 pad: conflict-free fragment loads
    __shared__ float As[128][BKP];
    __shared__ float Bs[128][BKP];

    const int tid  = threadIdx.x;
    const int wid  = tid >> 5;
    const int lane = tid & 31;
    const int wm   = wid >> 2;        // 0..1
    const int wn   = wid & 3;         // 0..3
    const int g    = lane >> 2;       // group 0..7
    const int t    = lane & 3;        // thread-in-group

    const int m0 = blockIdx.y * 128;
    const int n0 = blockIdx.x * 128;

    const int lrow = tid >> 2;            // 0..63
    const int lcol = (tid & 3) * 4;       // 0,4,8,12
    const float* Aptr = A  + (size_t)(m0 + lrow) * KDIM + lcol;
    const float* Bptr = BT + (size_t)(n0 + lrow) * KDIM + lcol;

    float4 pa0 = *(const float4*)(Aptr);
    float4 pa1 = *(const float4*)(Aptr + (size_t)64 * KDIM);
    float4 pb0 = *(const float4*)(Bptr);
    float4 pb1 = *(const float4*)(Bptr + (size_t)64 * KDIM);

    float acc[4][4][4] = {};

    constexpr int NCHUNK = KDIM / 16;   // 32
    #pragma unroll 1
    for (int kc = 0; kc < NCHUNK; kc++) {
        uint32_t* a0 = (uint32_t*)&As[lrow][lcol];
        a0[0] = f2tf32(pa0.x); a0[1] = f2tf32(pa0.y); a0[2] = f2tf32(pa0.z); a0[3] = f2tf32(pa0.w);
        uint32_t* a1 = (uint32_t*)&As[lrow + 64][lcol];
        a1[0] = f2tf32(pa1.x); a1[1] = f2tf32(pa1.y); a1[2] = f2tf32(pa1.z); a1[3] = f2tf32(pa1.w);
        uint32_t* b0 = (uint32_t*)&Bs[lrow][lcol];
        b0[0] = f2tf32(pb0.x); b0[1] = f2tf32(pb0.y); b0[2] = f2tf32(pb0.z); b0[3] = f2tf32(pb0.w);
        uint32_t* b1 = (uint32_t*)&Bs[lrow + 64][lcol];
        b1[0] = f2tf32(pb1.x); b1[1] = f2tf32(pb1.y); b1[2] = f2tf32(pb1.z); b1[3] = f2tf32(pb1.w);
        __syncthreads();

        if (kc + 1 < NCHUNK) {
            Aptr += 16; Bptr += 16;
            pa0 = *(const float4*)(Aptr);
            pa1 = *(const float4*)(Aptr + (size_t)64 * KDIM);
            pb0 = *(const float4*)(Bptr);
            pb1 = *(const float4*)(Bptr + (size_t)64 * KDIM);
        }

        #pragma unroll
        for (int ks = 0; ks < 2; ks++) {
            const int kb = ks * 8;
            uint32_t af[4][4], bf[4][2];
            #pragma unroll
            for (int mi = 0; mi < 4; mi++) {
                const int r = wm * 64 + mi * 16 + g;
                af[mi][0] = __float_as_uint(As[r][kb + t]);
                af[mi][1] = __float_as_uint(As[r + 8][kb + t]);
                af[mi][2] = __float_as_uint(As[r][kb + t + 4]);
                af[mi][3] = __float_as_uint(As[r + 8][kb + t + 4]);
            }
            #pragma unroll
            for (int ni = 0; ni < 4; ni++) {
                const int nr = wn * 32 + ni * 8 + g;
                bf[ni][0] = __float_as_uint(Bs[nr][kb + t]);
                bf[ni][1] = __float_as_uint(Bs[nr][kb + t + 4]);
            }
            #pragma unroll
            for (int mi = 0; mi < 4; mi++)
                #pragma unroll
                for (int ni = 0; ni < 4; ni++)
                    mma_tf32(acc[mi][ni], af[mi], bf[ni]);
        }
        __syncthreads();
    }

    #pragma unroll
    for (int mi = 0; mi < 4; mi++) {
        const int r = m0 + wm * 64 + mi * 16 + g;
        #pragma unroll
        for (int ni = 0; ni < 4; ni++) {
            const int c = n0 + wn * 32 + ni * 8 + 2 * t;
            const float bx0 = bias[c], bx1 = bias[c + 1];
            float2 v0 = make_float2(acc[mi][ni][0] + bx0, acc[mi][ni][1] + bx1);
            float2 v1 = make_float2(acc[mi][ni][2] + bx0, acc[mi][ni][3] + bx1);
            *(float2*)(C + (size_t)r * N + c)       = v0;
            *(float2*)(C + (size_t)(r + 8) * N + c) = v1;
        }
    }
}

// ---------------------------------------------------------------------------
// Sliding-window attention, register-tiled FFMA GEMM formulation.
// Block = 32 queries x (b,h). grid (S/32, H, B), 256 threads.
// Phase 1: S[32,96] = Q.K^T (warp tile 16x24, lane tile 4q x 3k)
// Softmax over rows (full window in smem), normalized in place.
// Phase 2: O[32,64] = P.V (warp tile 16q x 16d, lane tile 4q x 2d)
// V re-staged into the K buffer to stay under 48KB static smem.
// ---------------------------------------------------------------------------
#define QS_STR 68
#define KV_STR 68
#define SS_STR 100

__global__ __launch_bounds__(256)
void swin_attn(const float* __restrict__ qkv, float* __restrict__ att)
{
    __shared__ float sQ[32 * QS_STR];
    __shared__ float sKV[96 * KV_STR];
    __shared__ float sS[32 * SS_STR];

    const int t0 = blockIdx.x * 32;
    const int h  = blockIdx.y;
    const int b  = blockIdx.z;
    const int tid = threadIdx.x;

    // Stage Q rows t0..t0+31 (16 float4 per row)
    for (int i = tid; i < 32 * 16; i += 256) {
        const int r = i >> 4, c4 = (i & 15) << 2;
        *(float4*)&sQ[r * QS_STR + c4] =
            *(const float4*)(qkv + ((size_t)(b * S_ + t0 + r) * 3) * D_MODEL + h * HD + c4);
    }
    // Stage K rows t0-32 .. t0+63 (zero-fill out of range)
    for (int i = tid; i < 96 * 16; i += 256) {
        const int r = i >> 4, c4 = (i & 15) << 2;
        const int gr = t0 - 32 + r;
        float4 v = make_float4(0.f, 0.f, 0.f, 0.f);
        if (gr >= 0 && gr < S_)
            v = *(const float4*)(qkv + ((size_t)(b * S_ + gr) * 3) * D_MODEL + D_MODEL + h * HD + c4);
        *(float4*)&sKV[r * KV_STR + c4] = v;
    }
    __syncthreads();

    const int wid = tid >> 5, lane = tid & 31;
    const int wm = wid >> 2;          // 0..1  (query half)
    const int wn = wid & 3;           // 0..3  (key quarter)
    const int lq = lane & 3;          // 0..3
    const int lk = lane >> 2;         // 0..7

    // ---- Phase 1: scores ----
    {
        float acc[4][3] = {};
        const int qr0 = wm * 16 + lq;       // +4*i
        const int kr0 = wn * 24 + lk * 3;   // +j
        #pragma unroll
        for (int d = 0; d < HD; d += 4) {
            float4 a[4], bk[3];
            #pragma unroll
            for (int i = 0; i < 4; i++) a[i] = *(float4*)&sQ[(qr0 + 4 * i) * QS_STR + d];
            #pragma unroll
            for (int j = 0; j < 3; j++) bk[j] = *(float4*)&sKV[(kr0 + j) * KV_STR + d];
            #pragma unroll
            for (int i = 0; i < 4; i++)
                #pragma unroll
                for (int j = 0; j < 3; j++) {
                    acc[i][j] += a[i].x * bk[j].x + a[i].y * bk[j].y
                               + a[i].z * bk[j].z + a[i].w * bk[j].w;
                }
        }
        #pragma unroll
        for (int i = 0; i < 4; i++) {
            const int q = qr0 + 4 * i;
            #pragma unroll
            for (int j = 0; j < 3; j++) {
                const int kk = kr0 + j;
                const int gr = t0 - 32 + kk;
                const int dj = kk - 32 - q;
                const bool valid = (gr >= 0) && (gr < S_) && (dj >= -32) && (dj <= 32);
                sS[q * SS_STR + kk] = valid ? acc[i][j] * 0.125f : -1e30f;
            }
        }
    }
    __syncthreads();

    // ---- Stage V into sKV (K no longer needed) ----
    for (int i = tid; i < 96 * 16; i += 256) {
        const int r = i >> 4, c4 = (i & 15) << 2;
        const int gr = t0 - 32 + r;
        float4 v = make_float4(0.f, 0.f, 0.f, 0.f);
        if (gr >= 0 && gr < S_)
            v = *(const float4*)(qkv + ((size_t)(b * S_ + gr) * 3) * D_MODEL + 2 * D_MODEL + h * HD + c4);
        *(float4*)&sKV[r * KV_STR + c4] = v;
    }

    // ---- Softmax: warp handles rows wid*4 .. +3, normalize in place ----
    #pragma unroll
    for (int rr = 0; rr < 4; rr++) {
        const int q = wid * 4 + rr;
        float v0 = sS[q * SS_STR + lane];
        float v1 = sS[q * SS_STR + 32 + lane];
        float v2 = sS[q * SS_STR + 64 + lane];
        float m = fmaxf(v0, fmaxf(v1, v2));
        #pragma unroll
        for (int o = 16; o > 0; o >>= 1)
            m = fmaxf(m, __shfl_xor_sync(0xffffffffu, m, o));
        float e0 = __expf(v0 - m), e1 = __expf(v1 - m), e2 = __expf(v2 - m);
        float s = e0 + e1 + e2;
        #pragma unroll
        for (int o = 16; o > 0; o >>= 1)
            s += __shfl_xor_sync(0xffffffffu, s, o);
        const float inv = 1.0f / s;
        sS[q * SS_STR + lane]      = e0 * inv;
        sS[q * SS_STR + 32 + lane] = e1 * inv;
        sS[q * SS_STR + 64 + lane] = e2 * inv;
    }
    __syncthreads();

    // ---- Phase 2: O = P.V ----
    {
        float acc[4][2] = {};
        const int qr0 = wm * 16 + lq;        // +4*i
        const int dc  = wn * 16 + lk * 2;    // output dim pair
        #pragma unroll 4
        for (int j4 = 0; j4 < 96; j4 += 4) {
            float4 a[4];
            float2 bv[4];
            #pragma unroll
            for (int i = 0; i < 4; i++) a[i] = *(float4*)&sS[(qr0 + 4 * i) * SS_STR + j4];
            #pragma unroll
            for (int jj = 0; jj < 4; jj++) bv[jj] = *(float2*)&sKV[(j4 + jj) * KV_STR + dc];
            #pragma unroll
            for (int i = 0; i < 4; i++) {
                acc[i][0] += a[i].x * bv[0].x + a[i].y * bv[1].x + a[i].z * bv[2].x + a[i].w * bv[3].x;
                acc[i][1] += a[i].x * bv[0].y + a[i].y * bv[1].y + a[i].z * bv[2].y + a[i].w * bv[3].y;
            }
        }
        #pragma unroll
        for (int i = 0; i < 4; i++) {
            const int q = qr0 + 4 * i;
            *(float2*)(att + (size_t)(b * S_ + t0 + q) * D_MODEL + h * HD + dc) =
                make_float2(acc[i][0], acc[i][1]);
        }
    }
}

// ---------------------------------------------------------------------------
extern "C" void kernel_launch(void* const* d_in, const int* in_sizes, int n_in,
                              void* d_out, int out_size)
{
    const float* x     = (const float*)d_in[0];
    const float* w_qkv = (const float*)d_in[1];
    const float* b_qkv = (const float*)d_in[2];
    const float* w_out = (const float*)d_in[3];
    const float* b_out = (const float*)d_in[4];
    float* out = (float*)d_out;

    float *qkv, *att, *wqkvT, *woutT;
    cudaGetSymbolAddress((void**)&qkv, g_qkv);
    cudaGetSymbolAddress((void**)&att, g_att);
    cudaGetSymbolAddress((void**)&wqkvT, g_wqkvT);
    cudaGetSymbolAddress((void**)&woutT, g_woutT);

    // 0) Transpose weights: [K,N] -> [N,K]
    transpose_k<<<dim3(48, 16), dim3(32, 8)>>>(w_qkv, wqkvT, D_MODEL, 3 * D_MODEL);
    transpose_k<<<dim3(16, 16), dim3(32, 8)>>>(w_out, woutT, D_MODEL, D_MODEL);

    // 1) QKV projection: [4096,512] @ [512,1536] + bias
    gemm_tf32mma<1536><<<dim3(12, 32), 256>>>(x, wqkvT, b_qkv, qkv);

    // 2) Sliding-window attention
    swin_attn<<<dim3(S_ / 32, NHEAD, B_), 256>>>(qkv, att);

    // 3) Output projection: [4096,512] @ [512,512] + bias
    gemm_tf32mma<512><<<dim3(4, 32), 256>>>(att, woutT, b_out, out);
}

// round 15
// speedup vs baseline: 2.4824x; 1.1843x over previous
#include <cuda_runtime.h>
#include <cuda_bf16.h>
#include <cstdint>
#include <cstddef>

#define D_MODEL 512
#define NHEAD   8
#define HD      64
#define WIN     32
#define B_      2
#define S_      2048
#define MTOT    (B_ * S_)   // 4096
#define KDIM    512

// Scratch (device globals: allocation-free per harness rules)
__device__ float g_qkv[(size_t)MTOT * 3 * D_MODEL];      // [4096,1536]
__device__ float g_att[(size_t)MTOT * D_MODEL];          // [4096,512]

__device__ __forceinline__ uint32_t f2tf32(float f) {
    uint32_t u;
    asm("cvt.rna.tf32.f32 %0, %1;" : "=r"(u) : "f"(f));
    return u;
}

__device__ __forceinline__ void mma_tf32(float d[4], const uint32_t a[4], const uint32_t b[2]) {
    asm volatile(
        "mma.sync.aligned.m16n8k8.row.col.f32.tf32.tf32.f32 "
        "{%0,%1,%2,%3}, {%4,%5,%6,%7}, {%8,%9}, {%0,%1,%2,%3};"
        : "+f"(d[0]), "+f"(d[1]), "+f"(d[2]), "+f"(d[3])
        : "r"(a[0]), "r"(a[1]), "r"(a[2]), "r"(a[3]), "r"(b[0]), "r"(b[1]));
}

// ---------------------------------------------------------------------------
// tf32 mma.sync GEMM: C[M,N] = A[M,512] @ B[512,N] + bias[N]
// B consumed in native [K,N] layout (no pre-transpose).
// BM=BN=128, BK=16, 8 warps (2x4), warp tile 64x32, m16n8k8 fragments.
// ---------------------------------------------------------------------------
template <int N>
__global__ __launch_bounds__(256)
void gemm_tf32mma(const float* __restrict__ A, const float* __restrict__ B,
                  const float* __restrict__ bias, float* __restrict__ C)
{
    constexpr int AKP = 20;    // A tile stride (16 + 4 pad)
    constexpr int BNP = 132;   // B tile stride (128 + 4 pad)
    __shared__ float As[128][AKP];
    __shared__ float Bs[16][BNP];

    const int tid  = threadIdx.x;
    const int wid  = tid >> 5;
    const int lane = tid & 31;
    const int wm   = wid >> 2;        // 0..1
    const int wn   = wid & 3;         // 0..3
    const int g    = lane >> 2;       // group 0..7
    const int t    = lane & 3;        // thread-in-group

    const int m0 = blockIdx.y * 128;
    const int n0 = blockIdx.x * 128;

    // A global loads: thread -> rows (tid>>2), (tid>>2)+64, cols (tid&3)*4
    const int arow = tid >> 2;            // 0..63
    const int acol = (tid & 3) * 4;       // 0,4,8,12
    const float* Aptr = A + (size_t)(m0 + arow) * KDIM + acol;
    // B global loads: thread -> rows (tid>>5), (tid>>5)+8, cols (tid&31)*4
    const int brow = tid >> 5;            // 0..7
    const int bcol = (lane) * 4;          // 0..124
    const float* Bptr = B + (size_t)brow * N + n0 + bcol;

    float4 pa0 = *(const float4*)(Aptr);
    float4 pa1 = *(const float4*)(Aptr + (size_t)64 * KDIM);
    float4 pb0 = *(const float4*)(Bptr);
    float4 pb1 = *(const float4*)(Bptr + (size_t)8 * N);

    float acc[4][4][4] = {};

    constexpr int NCHUNK = KDIM / 16;   // 32
    #pragma unroll 1
    for (int kc = 0; kc < NCHUNK; kc++) {
        uint32_t* a0 = (uint32_t*)&As[arow][acol];
        a0[0] = f2tf32(pa0.x); a0[1] = f2tf32(pa0.y); a0[2] = f2tf32(pa0.z); a0[3] = f2tf32(pa0.w);
        uint32_t* a1 = (uint32_t*)&As[arow + 64][acol];
        a1[0] = f2tf32(pa1.x); a1[1] = f2tf32(pa1.y); a1[2] = f2tf32(pa1.z); a1[3] = f2tf32(pa1.w);
        uint32_t* b0 = (uint32_t*)&Bs[brow][bcol];
        b0[0] = f2tf32(pb0.x); b0[1] = f2tf32(pb0.y); b0[2] = f2tf32(pb0.z); b0[3] = f2tf32(pb0.w);
        uint32_t* b1 = (uint32_t*)&Bs[brow + 8][bcol];
        b1[0] = f2tf32(pb1.x); b1[1] = f2tf32(pb1.y); b1[2] = f2tf32(pb1.z); b1[3] = f2tf32(pb1.w);
        __syncthreads();

        if (kc + 1 < NCHUNK) {
            Aptr += 16;
            Bptr += (size_t)16 * N;
            pa0 = *(const float4*)(Aptr);
            pa1 = *(const float4*)(Aptr + (size_t)64 * KDIM);
            pb0 = *(const float4*)(Bptr);
            pb1 = *(const float4*)(Bptr + (size_t)8 * N);
        }

        #pragma unroll
        for (int ks = 0; ks < 2; ks++) {
            const int kb = ks * 8;
            uint32_t af[4][4], bf[4][2];
            #pragma unroll
            for (int mi = 0; mi < 4; mi++) {
                const int r = wm * 64 + mi * 16 + g;
                af[mi][0] = __float_as_uint(As[r][kb + t]);
                af[mi][1] = __float_as_uint(As[r + 8][kb + t]);
                af[mi][2] = __float_as_uint(As[r][kb + t + 4]);
                af[mi][3] = __float_as_uint(As[r + 8][kb + t + 4]);
            }
            #pragma unroll
            for (int ni = 0; ni < 4; ni++) {
                const int nc = wn * 32 + ni * 8 + g;
                bf[ni][0] = __float_as_uint(Bs[kb + t][nc]);
                bf[ni][1] = __float_as_uint(Bs[kb + t + 4][nc]);
            }
            #pragma unroll
            for (int mi = 0; mi < 4; mi++)
                #pragma unroll
                for (int ni = 0; ni < 4; ni++)
                    mma_tf32(acc[mi][ni], af[mi], bf[ni]);
        }
        __syncthreads();
    }

    #pragma unroll
    for (int mi = 0; mi < 4; mi++) {
        const int r = m0 + wm * 64 + mi * 16 + g;
        #pragma unroll
        for (int ni = 0; ni < 4; ni++) {
            const int c = n0 + wn * 32 + ni * 8 + 2 * t;
            const float bx0 = bias[c], bx1 = bias[c + 1];
            float2 v0 = make_float2(acc[mi][ni][0] + bx0, acc[mi][ni][1] + bx1);
            float2 v1 = make_float2(acc[mi][ni][2] + bx0, acc[mi][ni][3] + bx1);
            *(float2*)(C + (size_t)r * N + c)       = v0;
            *(float2*)(C + (size_t)(r + 8) * N + c) = v1;
        }
    }
}

// ---------------------------------------------------------------------------
// Sliding-window attention via mma.sync tf32.
// Block = 32 queries x (b,h). grid (S/32, H, B), 256 threads = 8 warps.
// Phase 1: S[32,96] = Q.K^T  (warp tile m16 x n24, contraction d=64)
// Softmax rows in fp32 smem; P stored back as tf32.
// Phase 2: O[32,64] = P.V    (warp tile m16 x n16, contraction k=96)
// ---------------------------------------------------------------------------
#define QS_STR 68
#define KV_STR 68
#define SS_STR 100

__global__ __launch_bounds__(256)
void swin_attn(const float* __restrict__ qkv, float* __restrict__ att)
{
    __shared__ float sQ[32 * QS_STR];
    __shared__ float sKV[96 * KV_STR];
    __shared__ float sS[32 * SS_STR];

    const int t0 = blockIdx.x * 32;
    const int h  = blockIdx.y;
    const int b  = blockIdx.z;
    const int tid = threadIdx.x;

    // Stage Q rows t0..t0+31 (tf32-rounded)
    for (int i = tid; i < 32 * 16; i += 256) {
        const int r = i >> 4, c4 = (i & 15) << 2;
        float4 v = *(const float4*)(qkv + ((size_t)(b * S_ + t0 + r) * 3) * D_MODEL + h * HD + c4);
        uint32_t* dst = (uint32_t*)&sQ[r * QS_STR + c4];
        dst[0] = f2tf32(v.x); dst[1] = f2tf32(v.y); dst[2] = f2tf32(v.z); dst[3] = f2tf32(v.w);
    }
    // Stage K rows t0-32 .. t0+63 (zero-fill out of range, tf32-rounded)
    for (int i = tid; i < 96 * 16; i += 256) {
        const int r = i >> 4, c4 = (i & 15) << 2;
        const int gr = t0 - 32 + r;
        float4 v = make_float4(0.f, 0.f, 0.f, 0.f);
        if (gr >= 0 && gr < S_)
            v = *(const float4*)(qkv + ((size_t)(b * S_ + gr) * 3) * D_MODEL + D_MODEL + h * HD + c4);
        uint32_t* dst = (uint32_t*)&sKV[r * KV_STR + c4];
        dst[0] = f2tf32(v.x); dst[1] = f2tf32(v.y); dst[2] = f2tf32(v.z); dst[3] = f2tf32(v.w);
    }
    __syncthreads();

    const int wid = tid >> 5, lane = tid & 31;
    const int wm = wid >> 2;          // 0..1  query half
    const int wn = wid & 3;           // 0..3
    const int g  = lane >> 2;         // 0..7
    const int t  = lane & 3;          // 0..3

    // ---- Phase 1: S = Q.K^T ----
    {
        float c[3][4] = {};
        const int qrow = wm * 16;
        #pragma unroll
        for (int ks = 0; ks < 8; ks++) {
            const int kb = ks * 8;
            uint32_t a[4];
            a[0] = __float_as_uint(sQ[(qrow + g) * QS_STR + kb + t]);
            a[1] = __float_as_uint(sQ[(qrow + g + 8) * QS_STR + kb + t]);
            a[2] = __float_as_uint(sQ[(qrow + g) * QS_STR + kb + t + 4]);
            a[3] = __float_as_uint(sQ[(qrow + g + 8) * QS_STR + kb + t + 4]);
            #pragma unroll
            for (int nt = 0; nt < 3; nt++) {
                const int nb = wn * 24 + nt * 8;
                uint32_t bv[2];
                bv[0] = __float_as_uint(sKV[(nb + g) * KV_STR + kb + t]);
                bv[1] = __float_as_uint(sKV[(nb + g) * KV_STR + kb + t + 4]);
                mma_tf32(c[nt], a, bv);
            }
        }
        // Write S with mask + scale. c layout: (g,2t),(g,2t+1),(g+8,2t),(g+8,2t+1)
        #pragma unroll
        for (int nt = 0; nt < 3; nt++) {
            #pragma unroll
            for (int e = 0; e < 4; e++) {
                const int q  = wm * 16 + g + (e >= 2 ? 8 : 0);
                const int kk = wn * 24 + nt * 8 + 2 * t + (e & 1);
                const int gr = t0 - 32 + kk;
                const int dj = kk - 32 - q;
                const bool valid = (gr >= 0) && (gr < S_) && (dj >= -32) && (dj <= 32);
                sS[q * SS_STR + kk] = valid ? c[nt][e] * 0.125f : -1e30f;
            }
        }
    }
    __syncthreads();

    // ---- Stage V into sKV (K no longer needed), tf32-rounded ----
    for (int i = tid; i < 96 * 16; i += 256) {
        const int r = i >> 4, c4 = (i & 15) << 2;
        const int gr = t0 - 32 + r;
        float4 v = make_float4(0.f, 0.f, 0.f, 0.f);
        if (gr >= 0 && gr < S_)
            v = *(const float4*)(qkv + ((size_t)(b * S_ + gr) * 3) * D_MODEL + 2 * D_MODEL + h * HD + c4);
        uint32_t* dst = (uint32_t*)&sKV[r * KV_STR + c4];
        dst[0] = f2tf32(v.x); dst[1] = f2tf32(v.y); dst[2] = f2tf32(v.z); dst[3] = f2tf32(v.w);
    }

    // ---- Softmax: warp handles rows wid*4..+3; store P as tf32 ----
    #pragma unroll
    for (int rr = 0; rr < 4; rr++) {
        const int q = wid * 4 + rr;
        float v0 = sS[q * SS_STR + lane];
        float v1 = sS[q * SS_STR + 32 + lane];
        float v2 = sS[q * SS_STR + 64 + lane];
        float m = fmaxf(v0, fmaxf(v1, v2));
        #pragma unroll
        for (int o = 16; o > 0; o >>= 1)
            m = fmaxf(m, __shfl_xor_sync(0xffffffffu, m, o));
        float e0 = __expf(v0 - m), e1 = __expf(v1 - m), e2 = __expf(v2 - m);
        float s = e0 + e1 + e2;
        #pragma unroll
        for (int o = 16; o > 0; o >>= 1)
            s += __shfl_xor_sync(0xffffffffu, s, o);
        const float inv = 1.0f / s;
        *(uint32_t*)&sS[q * SS_STR + lane]      = f2tf32(e0 * inv);
        *(uint32_t*)&sS[q * SS_STR + 32 + lane] = f2tf32(e1 * inv);
        *(uint32_t*)&sS[q * SS_STR + 64 + lane] = f2tf32(e2 * inv);
    }
    __syncthreads();

    // ---- Phase 2: O = P.V ----
    {
        float c[2][4] = {};
        const int qrow = wm * 16;
        #pragma unroll
        for (int ks = 0; ks < 12; ks++) {
            const int kb = ks * 8;
            uint32_t a[4];
            a[0] = __float_as_uint(sS[(qrow + g) * SS_STR + kb + t]);
            a[1] = __float_as_uint(sS[(qrow + g + 8) * SS_STR + kb + t]);
            a[2] = __float_as_uint(sS[(qrow + g) * SS_STR + kb + t + 4]);
            a[3] = __float_as_uint(sS[(qrow + g + 8) * SS_STR + kb + t + 4]);
            #pragma unroll
            for (int nt = 0; nt < 2; nt++) {
                const int nb = wn * 16 + nt * 8;
                uint32_t bv[2];
                bv[0] = __float_as_uint(sKV[(kb + t) * KV_STR + nb + g]);
                bv[1] = __float_as_uint(sKV[(kb + t + 4) * KV_STR + nb + g]);
                mma_tf32(c[nt], a, bv);
            }
        }
        #pragma unroll
        for (int nt = 0; nt < 2; nt++) {
            const int col = h * HD + wn * 16 + nt * 8 + 2 * t;
            const int q0 = t0 + wm * 16 + g;
            *(float2*)(att + (size_t)(b * S_ + q0) * D_MODEL + col) =
                make_float2(c[nt][0], c[nt][1]);
            *(float2*)(att + (size_t)(b * S_ + q0 + 8) * D_MODEL + col) =
                make_float2(c[nt][2], c[nt][3]);
        }
    }
}

// ---------------------------------------------------------------------------
extern "C" void kernel_launch(void* const* d_in, const int* in_sizes, int n_in,
                              void* d_out, int out_size)
{
    const float* x     = (const float*)d_in[0];
    const float* w_qkv = (const float*)d_in[1];
    const float* b_qkv = (const float*)d_in[2];
    const float* w_out = (const float*)d_in[3];
    const float* b_out = (const float*)d_in[4];
    float* out = (float*)d_out;

    float *qkv, *att;
    cudaGetSymbolAddress((void**)&qkv, g_qkv);
    cudaGetSymbolAddress((void**)&att, g_att);

    // 1) QKV projection: [4096,512] @ [512,1536] + bias
    gemm_tf32mma<1536><<<dim3(12, 32), 256>>>(x, w_qkv, b_qkv, qkv);

    // 2) Sliding-window attention
    swin_attn<<<dim3(S_ / 32, NHEAD, B_), 256>>>(qkv, att);

    // 3) Output projection: [4096,512] @ [512,512] + bias
    gemm_tf32mma<512><<<dim3(4, 32), 256>>>(att, w_out, b_out, out);
}